// round 1
// baseline (speedup 1.0000x reference)
#include <cuda_runtime.h>
#include <math.h>

#define BB   16
#define TT   1024
#define DIM  500
#define NROWS (BB*TT)

// ---------------- scratch (device globals; no allocation in kernel_launch) ---
__device__ float d_g[(size_t)NROWS*DIM];       // gcn_inputs (B*T, 500)
__device__ float d_key[(size_t)NROWS*DIM];
__device__ float d_query[(size_t)NROWS*DIM];
__device__ float d_value[(size_t)NROWS*DIM];
__device__ float d_S[(size_t)BB*TT*TT];        // S then P (in place)
__device__ float d_part[BB*8*DIM];             // partial max / partial sums
__device__ float d_subj[BB*DIM];
__device__ float d_qv[BB*DIM];
__device__ float d_tw[BB*DIM];                 // t * Wk
__device__ float d_cv[BB*DIM];
__device__ float d_m[BB*DIM];
__device__ float d_klog[BB*TT];
__device__ float d_kw[BB*TT];

// ---------------- helpers ----------------------------------------------------
__device__ __forceinline__ float warpSum(float v) {
    #pragma unroll
    for (int o = 16; o; o >>= 1) v += __shfl_xor_sync(0xffffffffu, v, o);
    return v;
}

// ---------------- 1) build g -------------------------------------------------
__global__ void build_g_kernel(
    const int* __restrict__ words, const int* __restrict__ pos,
    const int* __restrict__ ner, const int* __restrict__ chunks,
    const int* __restrict__ subj_pos, const int* __restrict__ obj_pos,
    const int* __restrict__ on_path, const float* __restrict__ dep_feat,
    const float* __restrict__ emb_w, const float* __restrict__ pos_w,
    const float* __restrict__ ner_w, const float* __restrict__ chunk_w,
    const float* __restrict__ position_w)
{
    int row = blockIdx.x;
    int d = threadIdx.x;
    if (d >= DIM) return;
    float v;
    if (d < 300)       v = emb_w[(size_t)words[row]*300 + d];
    else if (d < 335)  v = pos_w[pos[row]*35 + (d-300)];
    else if (d < 365)  v = ner_w[ner[row]*30 + (d-335)];
    else if (d < 395)  v = chunk_w[chunks[row]*30 + (d-365)];
    else if (d < 425)  v = position_w[subj_pos[row]*30 + (d-395)];
    else if (d < 455)  v = position_w[obj_pos[row]*30 + (d-425)];
    else if (d == 455) v = (float)on_path[row];
    else               v = dep_feat[(size_t)row*44 + (d-456)];
    d_g[(size_t)row*DIM + d] = v;
}

// ---------------- 2) subj max-pool (two stage) --------------------------------
__global__ void subj_partial_kernel(const int* __restrict__ subj_pos) {
    int b = blockIdx.x, ch = blockIdx.y;
    int d = threadIdx.x; if (d >= DIM) return;
    float mx = -3.4e38f;
    int base = b*TT + ch*128;
    for (int i = 0; i < 128; i++) {
        int row = base + i;
        float v = (subj_pos[row] != 0) ? -1.0e12f : d_g[(size_t)row*DIM + d];
        mx = fmaxf(mx, v);
    }
    d_part[(b*8+ch)*DIM + d] = mx;
}
__global__ void subj_reduce_kernel() {
    int b = blockIdx.x; int d = threadIdx.x; if (d >= DIM) return;
    float mx = d_part[(b*8)*DIM + d];
    #pragma unroll
    for (int c = 1; c < 8; c++) mx = fmaxf(mx, d_part[(b*8+c)*DIM + d]);
    d_subj[b*DIM + d] = mx;
}

// ---------------- 3) q = relu(so @ Wq + b); so=[s,s] --------------------------
__global__ void dense_q_kernel(const float* __restrict__ Wq_w, const float* __restrict__ Wq_b) {
    int b = blockIdx.x; int j = threadIdx.x;
    __shared__ float s[DIM];
    if (j < DIM) s[j] = d_subj[b*DIM + j];
    __syncthreads();
    if (j >= DIM) return;
    float acc = Wq_b[j];
    for (int d = 0; d < DIM; d++)
        acc = fmaf(s[d], Wq_w[d*DIM + j] + Wq_w[(d+DIM)*DIM + j], acc);
    d_qv[b*DIM + j] = fmaxf(acc, 0.f);
}

// ---------------- 4) t = relu(q @ Wc[0:500] + b); tw = t*Wk -------------------
__global__ void dense_t_kernel(const float* __restrict__ Wc_w, const float* __restrict__ Wc_b,
                               const float* __restrict__ Wk_w) {
    int b = blockIdx.x; int j = threadIdx.x;
    __shared__ float s[DIM];
    if (j < DIM) s[j] = d_qv[b*DIM + j];
    __syncthreads();
    if (j >= DIM) return;
    float acc = Wc_b[j];
    for (int d = 0; d < DIM; d++)
        acc = fmaf(s[d], Wc_w[d*DIM + j], acc);
    d_tw[b*DIM + j] = fmaxf(acc, 0.f) * Wk_w[j];
}

// ---------------- 5) k_logits[b,t] = dot(g_row, tw_b) + Wk_b ------------------
__global__ void klogit_kernel(const float* __restrict__ Wk_b) {
    int row = blockIdx.x; int b = row >> 10;
    int tid = threadIdx.x;
    const float* gr = d_g + (size_t)row*DIM;
    const float* tw = d_tw + b*DIM;
    float s = 0.f;
    for (int d = tid; d < DIM; d += 128) s = fmaf(gr[d], tw[d], s);
    s = warpSum(s);
    __shared__ float sm[4];
    if ((tid & 31) == 0) sm[tid >> 5] = s;
    __syncthreads();
    if (tid == 0) d_klog[row] = sm[0]+sm[1]+sm[2]+sm[3] + Wk_b[0];
}

// ---------------- 6) softmax over T of k_logits --------------------------------
__global__ void softmax_k_kernel() {
    int b = blockIdx.x, tid = threadIdx.x;
    __shared__ float red[256];
    const float* kr = d_klog + b*TT;
    float lmax = -3.4e38f;
    for (int t = tid; t < TT; t += 256) lmax = fmaxf(lmax, kr[t]);
    red[tid] = lmax; __syncthreads();
    for (int s = 128; s; s >>= 1) { if (tid < s) red[tid] = fmaxf(red[tid], red[tid+s]); __syncthreads(); }
    float m = red[0]; __syncthreads();
    float ls = 0.f;
    for (int t = tid; t < TT; t += 256) ls += expf(kr[t]-m);
    red[tid] = ls; __syncthreads();
    for (int s = 128; s; s >>= 1) { if (tid < s) red[tid] += red[tid+s]; __syncthreads(); }
    float inv = 1.f / red[0];
    for (int t = tid; t < TT; t += 256) d_kw[b*TT+t] = expf(kr[t]-m) * inv;
}

// ---------------- 7) c = sum_t k*g (two stage) --------------------------------
__global__ void c_partial_kernel() {
    int b = blockIdx.x, ch = blockIdx.y;
    int d = threadIdx.x; if (d >= DIM) return;
    float s = 0.f;
    int base = b*TT + ch*128;
    for (int i = 0; i < 128; i++) {
        int row = base + i;
        s = fmaf(d_kw[row], d_g[(size_t)row*DIM + d], s);
    }
    d_part[(b*8+ch)*DIM + d] = s;
}
__global__ void c_reduce_kernel() {
    int b = blockIdx.x; int d = threadIdx.x; if (d >= DIM) return;
    float s = 0.f;
    #pragma unroll
    for (int c = 0; c < 8; c++) s += d_part[(b*8+c)*DIM + d];
    d_cv[b*DIM + d] = s;
}

// ---------------- 8) m = relu([c, s, s] @ Wm + b) ------------------------------
__global__ void dense_m_kernel(const float* __restrict__ Wm_w, const float* __restrict__ Wm_b) {
    int b = blockIdx.x; int j = threadIdx.x;
    __shared__ float sc[DIM], ss[DIM];
    if (j < DIM) { sc[j] = d_cv[b*DIM + j]; ss[j] = d_subj[b*DIM + j]; }
    __syncthreads();
    if (j >= DIM) return;
    float acc = Wm_b[j];
    for (int d = 0; d < DIM; d++)
        acc = fmaf(sc[d], Wm_w[d*DIM + j], acc);
    for (int d = 0; d < DIM; d++)
        acc = fmaf(ss[d], Wm_w[(DIM+d)*DIM + j] + Wm_w[(2*DIM+d)*DIM + j], acc);
    d_m[b*DIM + j] = fmaxf(acc, 0.f);
}

// ---------------- generic 128x128x8 SGEMM (register-blocked) -------------------
// EPI: 0 none, 1 += bias[n], 2 *= ext[z*sExt + n]
template<bool BT, int EPI>
__global__ void __launch_bounds__(256)
gemm_kernel(const float* __restrict__ A, const float* __restrict__ Bm,
            float* __restrict__ C, int M, int N, int K,
            long sA, long sB, long sC,
            const float* __restrict__ ext, int sExt)
{
    __shared__ float As[8][128];
    __shared__ float Bs[8][128];
    const int z = blockIdx.z;
    const float* Ab = A + (size_t)z * sA;
    const float* Bb = Bm + (size_t)z * sB;
    float* Cb = C + (size_t)z * sC;
    const int m0 = blockIdx.y * 128, n0 = blockIdx.x * 128;
    const int tid = threadIdx.x;
    const int tx = tid & 15, ty = tid >> 4;

    float acc[8][8];
    #pragma unroll
    for (int i = 0; i < 8; i++)
        #pragma unroll
        for (int j = 0; j < 8; j++) acc[i][j] = 0.f;

    for (int k0 = 0; k0 < K; k0 += 8) {
        #pragma unroll
        for (int l = 0; l < 4; l++) {
            int i = tid + l*256;
            int m = i >> 3, k = i & 7;
            int gm = m0 + m, gk = k0 + k;
            As[k][m] = (gm < M && gk < K) ? Ab[(size_t)gm*K + gk] : 0.f;
        }
        #pragma unroll
        for (int l = 0; l < 4; l++) {
            int i = tid + l*256;
            if (BT) {
                int n = i >> 3, k = i & 7;
                int gn = n0 + n, gk = k0 + k;
                Bs[k][n] = (gn < N && gk < K) ? Bb[(size_t)gn*K + gk] : 0.f;
            } else {
                int k = i >> 7, n = i & 127;
                int gn = n0 + n, gk = k0 + k;
                Bs[k][n] = (gk < K && gn < N) ? Bb[(size_t)gk*N + gn] : 0.f;
            }
        }
        __syncthreads();
        #pragma unroll
        for (int k = 0; k < 8; k++) {
            float4 a0 = *(const float4*)&As[k][ty*8];
            float4 a1 = *(const float4*)&As[k][ty*8+4];
            float4 b0 = *(const float4*)&Bs[k][tx*8];
            float4 b1 = *(const float4*)&Bs[k][tx*8+4];
            float av[8] = {a0.x,a0.y,a0.z,a0.w,a1.x,a1.y,a1.z,a1.w};
            float bv[8] = {b0.x,b0.y,b0.z,b0.w,b1.x,b1.y,b1.z,b1.w};
            #pragma unroll
            for (int i = 0; i < 8; i++)
                #pragma unroll
                for (int j = 0; j < 8; j++)
                    acc[i][j] = fmaf(av[i], bv[j], acc[i][j]);
        }
        __syncthreads();
    }
    #pragma unroll
    for (int i = 0; i < 8; i++) {
        int gm = m0 + ty*8 + i;
        if (gm >= M) continue;
        #pragma unroll
        for (int j = 0; j < 8; j++) {
            int gn = n0 + tx*8 + j;
            if (gn >= N) continue;
            float v = acc[i][j];
            if (EPI == 1) v += ext[gn];
            else if (EPI == 2) v *= ext[(size_t)z*sExt + gn];
            Cb[(size_t)gm*N + gn] = v;
        }
    }
}

// ---------------- softmax over S rows: P in place + att ------------------------
__global__ void softmax_S_kernel(float* __restrict__ att) {
    int row = blockIdx.x;
    int t = row & (TT-1);
    int tid = threadIdx.x;
    __shared__ float srow[TT];
    __shared__ float red[256];
    float* Sr = d_S + (size_t)row * TT;

    for (int s = tid; s < TT; s += 256) srow[s] = Sr[s];
    __syncthreads();

    float lmax = -3.4e38f;
    for (int s = tid; s < TT; s += 256) lmax = fmaxf(lmax, srow[s]);
    red[tid] = lmax; __syncthreads();
    for (int s = 128; s; s >>= 1) { if (tid < s) red[tid] = fmaxf(red[tid], red[tid+s]); __syncthreads(); }
    float m1 = red[0]; __syncthreads();

    const float scale = sqrtf(500.f);
    const float invs = 1.f / scale;
    float s1 = 0.f, s2 = 0.f;
    for (int s = tid; s < TT; s += 256) {
        float x = srow[s] - m1;
        s1 += expf(x);
        s2 += expf(x * invs);
    }
    red[tid] = s1; __syncthreads();
    for (int s = 128; s; s >>= 1) { if (tid < s) red[tid] += red[tid+s]; __syncthreads(); }
    float S1 = red[0]; __syncthreads();
    red[tid] = s2; __syncthreads();
    for (int s = 128; s; s >>= 1) { if (tid < s) red[tid] += red[tid+s]; __syncthreads(); }
    float S2 = red[0]; __syncthreads();

    if (tid == 0)
        att[row] = (1.f - expf(srow[t] - m1) / S1) / scale;

    float invZ2 = 1.f / S2;
    for (int s = tid; s < TT; s += 256)
        Sr[s] = expf((srow[s] - m1) * invs) * invZ2;
}

// ---------------- launch -------------------------------------------------------
extern "C" void kernel_launch(void* const* d_in, const int* in_sizes, int n_in,
                              void* d_out, int out_size)
{
    const int*   words    = (const int*)d_in[0];
    /* d_in[1] = masks (unused by reference) */
    const int*   pos      = (const int*)d_in[2];
    const int*   ner      = (const int*)d_in[3];
    const int*   subj_pos = (const int*)d_in[4];
    const int*   obj_pos  = (const int*)d_in[5];
    const int*   chunks   = (const int*)d_in[6];
    const int*   on_path  = (const int*)d_in[7];
    const float* dep_feat = (const float*)d_in[8];
    const float* emb_w    = (const float*)d_in[9];
    const float* pos_w    = (const float*)d_in[10];
    const float* ner_w    = (const float*)d_in[11];
    const float* chunk_w  = (const float*)d_in[12];
    const float* position_w = (const float*)d_in[13];
    const float* Wq_w = (const float*)d_in[14]; const float* Wq_b = (const float*)d_in[15];
    const float* Wc_w = (const float*)d_in[16]; const float* Wc_b = (const float*)d_in[17];
    const float* Wk_w = (const float*)d_in[18]; const float* Wk_b = (const float*)d_in[19];
    const float* Wm_w = (const float*)d_in[20]; const float* Wm_b = (const float*)d_in[21];
    const float* K_w  = (const float*)d_in[22]; const float* K_b  = (const float*)d_in[23];
    const float* Q_w  = (const float*)d_in[24]; const float* Q_b  = (const float*)d_in[25];
    const float* V_w  = (const float*)d_in[26]; const float* V_b  = (const float*)d_in[27];

    float* out = (float*)d_out;                       // (B,T,D) flattened
    float* att = out + (size_t)NROWS * DIM;           // (B,T)

    float *g_p, *key_p, *query_p, *value_p, *S_p, *m_p;
    cudaGetSymbolAddress((void**)&g_p,     d_g);
    cudaGetSymbolAddress((void**)&key_p,   d_key);
    cudaGetSymbolAddress((void**)&query_p, d_query);
    cudaGetSymbolAddress((void**)&value_p, d_value);
    cudaGetSymbolAddress((void**)&S_p,     d_S);
    cudaGetSymbolAddress((void**)&m_p,     d_m);

    // 1. embeddings
    build_g_kernel<<<NROWS, 512>>>(words, pos, ner, chunks, subj_pos, obj_pos,
                                   on_path, dep_feat,
                                   emb_w, pos_w, ner_w, chunk_w, position_w);
    // 2. subj/obj max pool
    subj_partial_kernel<<<dim3(BB,8), 512>>>(subj_pos);
    subj_reduce_kernel<<<BB, 512>>>();
    // 3-8. attention-pool MLP chain
    dense_q_kernel<<<BB, 512>>>(Wq_w, Wq_b);
    dense_t_kernel<<<BB, 512>>>(Wc_w, Wc_b, Wk_w);
    klogit_kernel<<<NROWS, 128>>>(Wk_b);
    softmax_k_kernel<<<BB, 256>>>();
    c_partial_kernel<<<dim3(BB,8), 512>>>();
    c_reduce_kernel<<<BB, 512>>>();
    dense_m_kernel<<<BB, 512>>>(Wm_w, Wm_b);

    // 9. K/Q/V projections: (16384x500) @ (500x500) + bias
    gemm_kernel<false,1><<<dim3(4,128,1), 256>>>(g_p, K_w, key_p,   NROWS, DIM, DIM, 0,0,0, K_b, 0);
    gemm_kernel<false,1><<<dim3(4,128,1), 256>>>(g_p, Q_w, query_p, NROWS, DIM, DIM, 0,0,0, Q_b, 0);
    gemm_kernel<false,1><<<dim3(4,128,1), 256>>>(g_p, V_w, value_p, NROWS, DIM, DIM, 0,0,0, V_b, 0);

    // 10. S = key @ query^T (batched over B)
    gemm_kernel<true,0><<<dim3(8,8,BB), 256>>>(key_p, query_p, S_p, TT, TT, DIM,
                                               (long)TT*DIM, (long)TT*DIM, (long)TT*TT,
                                               nullptr, 0);
    // 11. dual softmax (att + P in place)
    softmax_S_kernel<<<NROWS, 256>>>(att);

    // 12. out = P @ value, fused with m* epilogue, written straight to d_out
    gemm_kernel<false,2><<<dim3(4,8,BB), 256>>>(S_p, value_p, out, TT, DIM, TT,
                                                (long)TT*TT, (long)TT*DIM, (long)TT*DIM,
                                                m_p, DIM);
}